// round 16
// baseline (speedup 1.0000x reference)
#include <cuda_runtime.h>
#include <cuda_bf16.h>
#include <mma.h>
#include <cstdint>

using namespace nvcuda;

#define N_NODES 100000
#define FDIM 128
#define MAX_E 1600000
#define NB_SCAN ((N_NODES + 1023) / 1024)   // 98

// ---------------- scratch (static device globals; no allocs allowed) -------
__device__ float g_norm_src[N_NODES];
__device__ float g_norm_dst[N_NODES];
__device__ float g_h1[(size_t)N_NODES * FDIM];
__device__ float g_h2[(size_t)N_NODES * FDIM];
__device__ uint32_t g_ahi[(size_t)N_NODES * (FDIM / 2)];  // agg hi, bf16x2
__device__ uint32_t g_alo[(size_t)N_NODES * (FDIM / 2)];  // agg lo, bf16x2
__device__ uint32_t g_w1hi[128 * 64], g_w1lo[128 * 64];   // W1 split (bf16x2)
__device__ uint32_t g_w2hi[128 * 64], g_w2lo[128 * 64];
__device__ uint32_t g_w3hi[128 * 128], g_w3lo[128 * 128];
__device__ int   g_src[MAX_E];
__device__ int   g_dst[MAX_E];
__device__ int   g_outdeg[N_NODES];
__device__ int   g_indeg[N_NODES];
__device__ int   g_cursor[N_NODES];
__device__ int   g_rowptr[N_NODES + 1];
__device__ int   g_blocksum[NB_SCAN];
__device__ int   g_csr_src[MAX_E];
__device__ unsigned g_odd_or;

// ---------------- edge dtype detection + normalization ----------------------
__global__ void detect_init_kernel() {
    if (threadIdx.x == 0 && blockIdx.x == 0) g_odd_or = 0u;
}
__global__ void detect_scan_kernel(const unsigned* __restrict__ w, int nwords) {
    int i = blockIdx.x * blockDim.x + threadIdx.x;
    unsigned v = 0;
    int idx = 2 * i + 1;
    if (idx < nwords) v = w[idx];
    unsigned any = __reduce_or_sync(0xFFFFFFFFu, v);
    if ((threadIdx.x & 31) == 0 && any) atomicOr(&g_odd_or, any);
}
__global__ void convert_edges_kernel(const void* __restrict__ ei, int E) {
    int i = blockIdx.x * blockDim.x + threadIdx.x;
    if (i >= 2 * E) return;
    bool is64 = (g_odd_or == 0u);
    int v = is64 ? (int)((const long long*)ei)[i] : ((const int*)ei)[i];
    if (i < E) g_src[i] = v;
    else       g_dst[i - E] = v;
}

// ---------------- degrees / norms -------------------------------------------
__global__ void zero_counts_kernel() {
    int i = blockIdx.x * blockDim.x + threadIdx.x;
    if (i < N_NODES) { g_outdeg[i] = 0; g_indeg[i] = 0; g_cursor[i] = 0; }
}
__global__ void degree_kernel(int E) {
    int i = blockIdx.x * blockDim.x + threadIdx.x;
    if (i < E) {
        atomicAdd(&g_outdeg[g_src[i]], 1);
        atomicAdd(&g_indeg[g_dst[i]], 1);
    }
}
__global__ void norm_kernel() {
    int i = blockIdx.x * blockDim.x + threadIdx.x;
    if (i < N_NODES) {
        int a = g_outdeg[i], b = g_indeg[i];
        g_norm_src[i] = (a > 0) ? rsqrtf((float)a) : 0.f;
        g_norm_dst[i] = (b > 0) ? rsqrtf((float)b) : 0.f;
    }
}

// ---------------- CSR build --------------------------------------------------
__global__ void scan1_kernel() {
    __shared__ int sh[1024];
    int tid = threadIdx.x;
    int i = blockIdx.x * 1024 + tid;
    int v = (i < N_NODES) ? g_indeg[i] : 0;
    sh[tid] = v;
    __syncthreads();
    for (int off = 1; off < 1024; off <<= 1) {
        int t = (tid >= off) ? sh[tid - off] : 0;
        __syncthreads();
        sh[tid] += t;
        __syncthreads();
    }
    if (i < N_NODES) g_rowptr[i] = sh[tid] - v;
    if (tid == 1023) g_blocksum[blockIdx.x] = sh[1023];
}
__global__ void scan2_kernel() {
    __shared__ int sh[128];
    int tid = threadIdx.x;
    int v = (tid < NB_SCAN) ? g_blocksum[tid] : 0;
    sh[tid] = v;
    __syncthreads();
    for (int off = 1; off < 128; off <<= 1) {
        int t = (tid >= off) ? sh[tid - off] : 0;
        __syncthreads();
        sh[tid] += t;
        __syncthreads();
    }
    if (tid < NB_SCAN) g_blocksum[tid] = sh[tid] - v;
}
__global__ void scan3_kernel(int E) {
    int i = blockIdx.x * blockDim.x + threadIdx.x;
    if (i < N_NODES) g_rowptr[i] += g_blocksum[i >> 10];
    if (i == 0) g_rowptr[N_NODES] = E;
}
__global__ void fill_csr_kernel(int E) {
    int e = blockIdx.x * blockDim.x + threadIdx.x;
    if (e >= E) return;
    int d = g_dst[e];
    int pos = g_rowptr[d] + atomicAdd(&g_cursor[d], 1);
    g_csr_src[pos] = g_src[e];
}

// ---------------- weight pre-split ------------------------------------------
__global__ void wsplit_kernel(const float* __restrict__ W,
                              uint32_t* __restrict__ whi,
                              uint32_t* __restrict__ wlo, int npairs) {
    int i = blockIdx.x * blockDim.x + threadIdx.x;
    if (i >= npairs) return;
    float2 v = *(const float2*)(W + 2 * i);
    __nv_bfloat16 h0 = __float2bfloat16(v.x);
    __nv_bfloat16 h1 = __float2bfloat16(v.y);
    __nv_bfloat162 hp(h0, h1);
    __nv_bfloat162 lp(__float2bfloat16(v.x - __bfloat162float(h0)),
                      __float2bfloat16(v.y - __bfloat162float(h1)));
    whi[i] = *(uint32_t*)&hp;
    wlo[i] = *(uint32_t*)&lp;
}

// ---------------- gather: R11-style loads + fused hi/lo split ----------------
// one warp per dst node; direct uniform index loads (L1-broadcast), unroll-4.
template <int SRCSEL>
__global__ void gather_kernel(const float* __restrict__ xin) {
    const float* in = (SRCSEL == 0) ? xin : (SRCSEL == 1 ? g_h1 : g_h2);
    int node = blockIdx.x * (blockDim.x >> 5) + (threadIdx.x >> 5);
    if (node >= N_NODES) return;
    int lane = threadIdx.x & 31;
    int beg = g_rowptr[node], end = g_rowptr[node + 1];

    float ax = 0.f, ay = 0.f, az = 0.f, aw = 0.f;
    int i = beg;
    for (; i + 4 <= end; i += 4) {
        int s0 = g_csr_src[i + 0], s1 = g_csr_src[i + 1];
        int s2 = g_csr_src[i + 2], s3 = g_csr_src[i + 3];
        float n0 = g_norm_src[s0], n1 = g_norm_src[s1];
        float n2 = g_norm_src[s2], n3 = g_norm_src[s3];
        float4 v0 = *(const float4*)(in + (size_t)s0 * FDIM + lane * 4);
        float4 v1 = *(const float4*)(in + (size_t)s1 * FDIM + lane * 4);
        float4 v2 = *(const float4*)(in + (size_t)s2 * FDIM + lane * 4);
        float4 v3 = *(const float4*)(in + (size_t)s3 * FDIM + lane * 4);
        ax = fmaf(v0.x, n0, ax); ay = fmaf(v0.y, n0, ay); az = fmaf(v0.z, n0, az); aw = fmaf(v0.w, n0, aw);
        ax = fmaf(v1.x, n1, ax); ay = fmaf(v1.y, n1, ay); az = fmaf(v1.z, n1, az); aw = fmaf(v1.w, n1, aw);
        ax = fmaf(v2.x, n2, ax); ay = fmaf(v2.y, n2, ay); az = fmaf(v2.z, n2, az); aw = fmaf(v2.w, n2, aw);
        ax = fmaf(v3.x, n3, ax); ay = fmaf(v3.y, n3, ay); az = fmaf(v3.z, n3, az); aw = fmaf(v3.w, n3, aw);
    }
    for (; i < end; ++i) {
        int s = g_csr_src[i];
        float ns = g_norm_src[s];
        float4 v = *(const float4*)(in + (size_t)s * FDIM + lane * 4);
        ax = fmaf(v.x, ns, ax); ay = fmaf(v.y, ns, ay);
        az = fmaf(v.z, ns, az); aw = fmaf(v.w, ns, aw);
    }
    float nd = g_norm_dst[node];
    ax *= nd; ay *= nd; az *= nd; aw *= nd;

    // fused hi/lo bf16 split (numerically = R11's GEMM prologue)
    __nv_bfloat16 hx = __float2bfloat16(ax), hy = __float2bfloat16(ay);
    __nv_bfloat16 hz = __float2bfloat16(az), hw = __float2bfloat16(aw);
    __nv_bfloat162 hp0(hx, hy), hp1(hz, hw);
    __nv_bfloat162 lp0(__float2bfloat16(ax - __bfloat162float(hx)),
                       __float2bfloat16(ay - __bfloat162float(hy)));
    __nv_bfloat162 lp1(__float2bfloat16(az - __bfloat162float(hz)),
                       __float2bfloat16(aw - __bfloat162float(hw)));
    uint2 hv = make_uint2(*(uint32_t*)&hp0, *(uint32_t*)&hp1);
    uint2 lv = make_uint2(*(uint32_t*)&lp0, *(uint32_t*)&lp1);
    *(uint2*)(g_ahi + (size_t)node * 64 + lane * 2) = hv;
    *(uint2*)(g_alo + (size_t)node * 64 + lane * 2) = lv;
}

// ---------------- WMMA split-bf16 GEMM (R11 structure, pre-split inputs) -----
// One CTA per 128x64 output tile, grid (NC/64, ceil(N/128)) — R11's shape.
#define LDA 136
#define LDB 72

template <int NC, bool RELU, int DSTSEL>
__global__ __launch_bounds__(256) void wmma_gemm_kernel(
    const uint32_t* __restrict__ Whi, const uint32_t* __restrict__ Wlo,
    const float* __restrict__ bias, float* __restrict__ outp) {
    float* out = (DSTSEL == 0) ? outp : (DSTSEL == 1 ? g_h1 : g_h2);

    __shared__ __align__(16) __nv_bfloat16 sAhi[128 * LDA];   // 34816 B
    __shared__ __align__(16) __nv_bfloat16 sAlo[128 * LDA];   // 34816 B
    __shared__ __align__(16) __nv_bfloat16 sBhi[128 * LDB];   // 18432 B
    __shared__ __align__(16) __nv_bfloat16 sBlo[128 * LDB];   // 18432 B

    const int tid = threadIdx.x;
    const int wid = tid >> 5;
    const int lane = tid & 31;
    const int row0 = blockIdx.y * 128;
    const int col0 = blockIdx.x * 64;

    // ---- A tile: 128 rows x 128 k, bf16 pre-split (guarded uint4 loads)
    for (int i = tid; i < 128 * 16; i += 256) {
        int m = i >> 4, k8 = (i & 15);       // 8 bf16 per uint4
        int gr = row0 + m;
        uint4 h = make_uint4(0, 0, 0, 0), l = make_uint4(0, 0, 0, 0);
        if (gr < N_NODES) {
            h = *(const uint4*)(g_ahi + (size_t)gr * 64 + k8 * 4);
            l = *(const uint4*)(g_alo + (size_t)gr * 64 + k8 * 4);
        }
        *(uint4*)(sAhi + m * LDA + k8 * 8) = h;
        *(uint4*)(sAlo + m * LDA + k8 * 8) = l;
    }
    // ---- B tile: 128 k x 64 n (bf16 pre-split)
    for (int i = tid; i < 128 * 8; i += 256) {
        int k = i >> 3, n8 = (i & 7);        // 8 bf16 per uint4
        uint4 h = *(const uint4*)(Whi + (size_t)k * (NC / 2) + blockIdx.x * 32 + n8 * 4);
        uint4 l = *(const uint4*)(Wlo + (size_t)k * (NC / 2) + blockIdx.x * 32 + n8 * 4);
        *(uint4*)(sBhi + k * LDB + n8 * 8) = h;
        *(uint4*)(sBlo + k * LDB + n8 * 8) = l;
    }
    __syncthreads();

    // warp grid: 4 (M) x 2 (N); warp tile 32x32 = 2x2 wmma 16x16x16 frags
    const int wm = wid & 3, wn = wid >> 2;
    wmma::fragment<wmma::accumulator, 16, 16, 16, float> c[2][2];
#pragma unroll
    for (int i = 0; i < 2; ++i)
#pragma unroll
        for (int j = 0; j < 2; ++j) wmma::fill_fragment(c[i][j], 0.f);

#pragma unroll
    for (int kk = 0; kk < 8; ++kk) {
        wmma::fragment<wmma::matrix_a, 16, 16, 16, __nv_bfloat16, wmma::row_major> ah[2], al[2];
        wmma::fragment<wmma::matrix_b, 16, 16, 16, __nv_bfloat16, wmma::row_major> bh[2], bl[2];
#pragma unroll
        for (int i = 0; i < 2; ++i) {
            const int r = (wm * 32 + i * 16) * LDA + kk * 16;
            wmma::load_matrix_sync(ah[i], sAhi + r, LDA);
            wmma::load_matrix_sync(al[i], sAlo + r, LDA);
        }
#pragma unroll
        for (int j = 0; j < 2; ++j) {
            const int r = (kk * 16) * LDB + wn * 32 + j * 16;
            wmma::load_matrix_sync(bh[j], sBhi + r, LDB);
            wmma::load_matrix_sync(bl[j], sBlo + r, LDB);
        }
#pragma unroll
        for (int i = 0; i < 2; ++i)
#pragma unroll
            for (int j = 0; j < 2; ++j) {
                wmma::mma_sync(c[i][j], ah[i], bh[j], c[i][j]);
                wmma::mma_sync(c[i][j], ah[i], bl[j], c[i][j]);
                wmma::mma_sync(c[i][j], al[i], bh[j], c[i][j]);
            }
    }

    // ---- epilogue (R11-style): stage frags through reused A region
    __syncthreads();
    float* stg = (float*)sAhi + wid * 1280;   // per-warp [32][40]
#pragma unroll
    for (int i = 0; i < 2; ++i)
#pragma unroll
        for (int j = 0; j < 2; ++j)
            wmma::store_matrix_sync(stg + i * 16 * 40 + j * 16, c[i][j], 40,
                                    wmma::mem_row_major);
    __syncwarp();

    int gr = row0 + wm * 32 + lane;
    if (gr < N_NODES) {
        const int cbase = col0 + wn * 32;
#pragma unroll
        for (int c4 = 0; c4 < 8; ++c4) {
            float4 bv = *(const float4*)(bias + cbase + c4 * 4);
            float4 v  = *(const float4*)(stg + lane * 40 + c4 * 4);
            float4 o;
            o.x = v.x + bv.x; o.y = v.y + bv.y;
            o.z = v.z + bv.z; o.w = v.w + bv.w;
            if (RELU) {
                o.x = fmaxf(o.x, 0.f); o.y = fmaxf(o.y, 0.f);
                o.z = fmaxf(o.z, 0.f); o.w = fmaxf(o.w, 0.f);
            }
            *(float4*)(out + (size_t)gr * NC + cbase + c4 * 4) = o;
        }
    }
}

// ---------------- edge_index tail -------------------------------------------
__global__ void edge_cast_kernel(float* __restrict__ out, int E) {
    int i = blockIdx.x * blockDim.x + threadIdx.x;
    if (i >= 2 * E) return;
    int v = (i < E) ? g_src[i] : g_dst[i - E];
    out[i] = (float)v;
}
__global__ void edge_copy64_kernel(long long* __restrict__ out, int E) {
    int i = blockIdx.x * blockDim.x + threadIdx.x;
    if (i >= 2 * E) return;
    int v = (i < E) ? g_src[i] : g_dst[i - E];
    out[i] = (long long)v;
}

// ---------------- launch -----------------------------------------------------
extern "C" void kernel_launch(void* const* d_in, const int* in_sizes, int n_in,
                              void* d_out, int out_size) {
    const float* x  = (const float*)d_in[0];
    const void*  ei = d_in[1];
    const float* W1 = (const float*)d_in[2];
    const float* b1 = (const float*)d_in[3];
    const float* W2 = (const float*)d_in[4];
    const float* b2 = (const float*)d_in[5];
    const float* W3 = (const float*)d_in[6];
    const float* b3 = (const float*)d_in[7];
    float* out = (float*)d_out;

    const int E = in_sizes[1] / 2;

    const int NTHR = 256;
    const int nodeBlocks  = (N_NODES + NTHR - 1) / NTHR;
    const int edgeBlocks  = (E + NTHR - 1) / NTHR;
    const int edge2Blocks = (2 * E + NTHR - 1) / NTHR;
    const int gatherBlocks = (N_NODES + 7) / 8;
    const dim3 g128(2, (N_NODES + 127) / 128);   // R11 grid shape
    const dim3 g256(4, (N_NODES + 127) / 128);

    // edge dtype detection + normalization
    detect_init_kernel<<<1, 32>>>();
    detect_scan_kernel<<<edgeBlocks, NTHR>>>((const unsigned*)ei, 2 * E);
    convert_edges_kernel<<<edge2Blocks, NTHR>>>(ei, E);

    // weight pre-split (independent of edges)
    wsplit_kernel<<<(128 * 64 + NTHR - 1) / NTHR, NTHR>>>(W1, g_w1hi, g_w1lo, 128 * 64);
    wsplit_kernel<<<(128 * 64 + NTHR - 1) / NTHR, NTHR>>>(W2, g_w2hi, g_w2lo, 128 * 64);
    wsplit_kernel<<<(128 * 128 + NTHR - 1) / NTHR, NTHR>>>(W3, g_w3hi, g_w3lo, 128 * 128);

    // degrees -> norms, CSR build
    zero_counts_kernel<<<nodeBlocks, NTHR>>>();
    degree_kernel<<<edgeBlocks, NTHR>>>(E);
    norm_kernel<<<nodeBlocks, NTHR>>>();
    scan1_kernel<<<NB_SCAN, 1024>>>();
    scan2_kernel<<<1, 128>>>();
    scan3_kernel<<<nodeBlocks, NTHR>>>(E);
    fill_csr_kernel<<<edgeBlocks, NTHR>>>(E);

    // layer 1: x -> g_h1
    gather_kernel<0><<<gatherBlocks, NTHR>>>(x);
    wmma_gemm_kernel<128, true, 1><<<g128, NTHR>>>(g_w1hi, g_w1lo, b1, nullptr);

    // layer 2: g_h1 -> g_h2
    gather_kernel<1><<<gatherBlocks, NTHR>>>(nullptr);
    wmma_gemm_kernel<128, true, 2><<<g128, NTHR>>>(g_w2hi, g_w2lo, b2, nullptr);

    // layer 3: g_h2 -> out, 256 cols, no relu
    gather_kernel<2><<<gatherBlocks, NTHR>>>(nullptr);
    wmma_gemm_kernel<256, false, 0><<<g256, NTHR>>>(g_w3hi, g_w3lo, b3, out);

    // tuple tail: edge_index passthrough, if the harness compares it
    const long long HOUT = (long long)N_NODES * 256;
    const long long extra = (long long)out_size - HOUT;
    if (extra == 2LL * E) {
        edge_cast_kernel<<<edge2Blocks, NTHR>>>(out + HOUT, E);
    } else if (extra == 4LL * E) {
        edge_copy64_kernel<<<edge2Blocks, NTHR>>>((long long*)(out + HOUT), E);
    }
}

// round 17
// speedup vs baseline: 2.3948x; 2.3948x over previous
#include <cuda_runtime.h>
#include <cuda_bf16.h>
#include <mma.h>
#include <cstdint>

using namespace nvcuda;

#define N_NODES 100000
#define FDIM 128
#define MAX_E 1600000
#define NB_SCAN ((N_NODES + 1023) / 1024)   // 98

// ---------------- scratch (static device globals; no allocs allowed) -------
__device__ float g_norm_src[N_NODES];
__device__ float g_norm_dst[N_NODES];
__device__ float g_agg[(size_t)N_NODES * FDIM];
__device__ float g_h1[(size_t)N_NODES * FDIM];
__device__ float g_h2[(size_t)N_NODES * FDIM];
__device__ int   g_src[MAX_E];
__device__ int   g_dst[MAX_E];
__device__ int   g_outdeg[N_NODES];
__device__ int   g_indeg[N_NODES];
__device__ int   g_cursor[N_NODES];
__device__ int   g_rowptr[N_NODES + 1];
__device__ int   g_blocksum[NB_SCAN];
__device__ int   g_csr_src[MAX_E];
__device__ unsigned g_odd_or;

// ---------------- edge dtype detection + normalization ----------------------
__global__ void detect_init_kernel() {
    if (threadIdx.x == 0 && blockIdx.x == 0) g_odd_or = 0u;
}
__global__ void detect_scan_kernel(const unsigned* __restrict__ w, int nwords) {
    int i = blockIdx.x * blockDim.x + threadIdx.x;
    unsigned v = 0;
    int idx = 2 * i + 1;
    if (idx < nwords) v = w[idx];
    unsigned any = __reduce_or_sync(0xFFFFFFFFu, v);
    if ((threadIdx.x & 31) == 0 && any) atomicOr(&g_odd_or, any);
}
__global__ void convert_edges_kernel(const void* __restrict__ ei, int E) {
    int i = blockIdx.x * blockDim.x + threadIdx.x;
    if (i >= 2 * E) return;
    bool is64 = (g_odd_or == 0u);
    int v = is64 ? (int)((const long long*)ei)[i] : ((const int*)ei)[i];
    if (i < E) g_src[i] = v;
    else       g_dst[i - E] = v;
}

// ---------------- degrees / norms -------------------------------------------
__global__ void zero_counts_kernel() {
    int i = blockIdx.x * blockDim.x + threadIdx.x;
    if (i < N_NODES) { g_outdeg[i] = 0; g_indeg[i] = 0; g_cursor[i] = 0; }
}
__global__ void degree_kernel(int E) {
    int i = blockIdx.x * blockDim.x + threadIdx.x;
    if (i < E) {
        atomicAdd(&g_outdeg[g_src[i]], 1);
        atomicAdd(&g_indeg[g_dst[i]], 1);
    }
}
__global__ void norm_kernel() {
    int i = blockIdx.x * blockDim.x + threadIdx.x;
    if (i < N_NODES) {
        int a = g_outdeg[i], b = g_indeg[i];
        g_norm_src[i] = (a > 0) ? rsqrtf((float)a) : 0.f;
        g_norm_dst[i] = (b > 0) ? rsqrtf((float)b) : 0.f;
    }
}

// ---------------- CSR build --------------------------------------------------
__global__ void scan1_kernel() {
    __shared__ int sh[1024];
    int tid = threadIdx.x;
    int i = blockIdx.x * 1024 + tid;
    int v = (i < N_NODES) ? g_indeg[i] : 0;
    sh[tid] = v;
    __syncthreads();
    for (int off = 1; off < 1024; off <<= 1) {
        int t = (tid >= off) ? sh[tid - off] : 0;
        __syncthreads();
        sh[tid] += t;
        __syncthreads();
    }
    if (i < N_NODES) g_rowptr[i] = sh[tid] - v;
    if (tid == 1023) g_blocksum[blockIdx.x] = sh[1023];
}
__global__ void scan2_kernel() {
    __shared__ int sh[128];
    int tid = threadIdx.x;
    int v = (tid < NB_SCAN) ? g_blocksum[tid] : 0;
    sh[tid] = v;
    __syncthreads();
    for (int off = 1; off < 128; off <<= 1) {
        int t = (tid >= off) ? sh[tid - off] : 0;
        __syncthreads();
        sh[tid] += t;
        __syncthreads();
    }
    if (tid < NB_SCAN) g_blocksum[tid] = sh[tid] - v;
}
__global__ void scan3_kernel(int E) {
    int i = blockIdx.x * blockDim.x + threadIdx.x;
    if (i < N_NODES) g_rowptr[i] += g_blocksum[i >> 10];
    if (i == 0) g_rowptr[N_NODES] = E;
}
__global__ void fill_csr_kernel(int E) {
    int e = blockIdx.x * blockDim.x + threadIdx.x;
    if (e >= E) return;
    int d = g_dst[e];
    int pos = g_rowptr[d] + atomicAdd(&g_cursor[d], 1);
    g_csr_src[pos] = g_src[e];
}

// ---------------- gather ------------------------------------------------------
template <int SRCSEL>
__global__ void gather_kernel(const float* __restrict__ xin) {
    const float* in = (SRCSEL == 0) ? xin : (SRCSEL == 1 ? g_h1 : g_h2);
    int node = blockIdx.x * (blockDim.x >> 5) + (threadIdx.x >> 5);
    if (node >= N_NODES) return;
    int lane = threadIdx.x & 31;
    int beg = g_rowptr[node], end = g_rowptr[node + 1];

    float ax = 0.f, ay = 0.f, az = 0.f, aw = 0.f;
    int i = beg;
    for (; i + 4 <= end; i += 4) {
        int s0 = g_csr_src[i + 0], s1 = g_csr_src[i + 1];
        int s2 = g_csr_src[i + 2], s3 = g_csr_src[i + 3];
        float n0 = g_norm_src[s0], n1 = g_norm_src[s1];
        float n2 = g_norm_src[s2], n3 = g_norm_src[s3];
        float4 v0 = *(const float4*)(in + (size_t)s0 * FDIM + lane * 4);
        float4 v1 = *(const float4*)(in + (size_t)s1 * FDIM + lane * 4);
        float4 v2 = *(const float4*)(in + (size_t)s2 * FDIM + lane * 4);
        float4 v3 = *(const float4*)(in + (size_t)s3 * FDIM + lane * 4);
        ax = fmaf(v0.x, n0, ax); ay = fmaf(v0.y, n0, ay); az = fmaf(v0.z, n0, az); aw = fmaf(v0.w, n0, aw);
        ax = fmaf(v1.x, n1, ax); ay = fmaf(v1.y, n1, ay); az = fmaf(v1.z, n1, az); aw = fmaf(v1.w, n1, aw);
        ax = fmaf(v2.x, n2, ax); ay = fmaf(v2.y, n2, ay); az = fmaf(v2.z, n2, az); aw = fmaf(v2.w, n2, aw);
        ax = fmaf(v3.x, n3, ax); ay = fmaf(v3.y, n3, ay); az = fmaf(v3.z, n3, az); aw = fmaf(v3.w, n3, aw);
    }
    for (; i < end; ++i) {
        int s = g_csr_src[i];
        float ns = g_norm_src[s];
        float4 v = *(const float4*)(in + (size_t)s * FDIM + lane * 4);
        ax = fmaf(v.x, ns, ax); ay = fmaf(v.y, ns, ay);
        az = fmaf(v.z, ns, az); aw = fmaf(v.w, ns, aw);
    }
    float nd = g_norm_dst[node];
    *(float4*)(g_agg + (size_t)node * FDIM + lane * 4) =
        make_float4(ax * nd, ay * nd, az * nd, aw * nd);
}

// ---------------- WMMA split-bf16 GEMM ---------------------------------------
// out[128 x 64 per CTA] = g_agg @ W (+bias, relu?)
// A,B split to bf16 hi/lo; D = Ahi*Bhi + Ahi*Blo + Alo*Bhi, fp32 accum.
#define LDA 136
#define LDB 72
#define OFF_ALO 34816
#define OFF_BHI 69632
#define OFF_BLO 88064
#define SMEM_BYTES 106496

__device__ __forceinline__ void split2(float x0, float x1,
                                       __nv_bfloat162& hi, __nv_bfloat162& lo) {
    __nv_bfloat16 h0 = __float2bfloat16(x0);
    __nv_bfloat16 h1 = __float2bfloat16(x1);
    hi = __nv_bfloat162(h0, h1);
    lo = __nv_bfloat162(__float2bfloat16(x0 - __bfloat162float(h0)),
                        __float2bfloat16(x1 - __bfloat162float(h1)));
}

template <int NC, bool RELU, int DSTSEL>
__global__ __launch_bounds__(256) void wmma_gemm_kernel(
    const float* __restrict__ W, const float* __restrict__ bias,
    float* __restrict__ outp) {
    float* out = (DSTSEL == 0) ? outp : (DSTSEL == 1 ? g_h1 : g_h2);

    __shared__ __align__(256) char s_raw[SMEM_BYTES];
    __nv_bfloat16* sAhi = (__nv_bfloat16*)s_raw;
    __nv_bfloat16* sAlo = (__nv_bfloat16*)(s_raw + OFF_ALO);
    __nv_bfloat16* sBhi = (__nv_bfloat16*)(s_raw + OFF_BHI);
    __nv_bfloat16* sBlo = (__nv_bfloat16*)(s_raw + OFF_BLO);

    const int tid = threadIdx.x;
    const int wid = tid >> 5;
    const int lane = tid & 31;
    const int row0 = blockIdx.y * 128;
    const int col0 = blockIdx.x * 64;

    // A tile: 128 rows x 128 k -> hi/lo bf16
    for (int i = tid; i < 128 * 32; i += 256) {
        int m = i >> 5, k4 = (i & 31) * 4;
        int gr = row0 + m;
        float4 v = (gr < N_NODES)
                       ? *(const float4*)(g_agg + (size_t)gr * FDIM + k4)
                       : make_float4(0.f, 0.f, 0.f, 0.f);
        __nv_bfloat162 h0, l0, h1, l1;
        split2(v.x, v.y, h0, l0);
        split2(v.z, v.w, h1, l1);
        *(__nv_bfloat162*)(sAhi + m * LDA + k4)     = h0;
        *(__nv_bfloat162*)(sAhi + m * LDA + k4 + 2) = h1;
        *(__nv_bfloat162*)(sAlo + m * LDA + k4)     = l0;
        *(__nv_bfloat162*)(sAlo + m * LDA + k4 + 2) = l1;
    }
    // B tile: 128 k x 64 n -> hi/lo bf16
    for (int i = tid; i < 128 * 16; i += 256) {
        int k = i >> 4, n4 = (i & 15) * 4;
        float4 v = *(const float4*)(W + (size_t)k * NC + col0 + n4);
        __nv_bfloat162 h0, l0, h1, l1;
        split2(v.x, v.y, h0, l0);
        split2(v.z, v.w, h1, l1);
        *(__nv_bfloat162*)(sBhi + k * LDB + n4)     = h0;
        *(__nv_bfloat162*)(sBhi + k * LDB + n4 + 2) = h1;
        *(__nv_bfloat162*)(sBlo + k * LDB + n4)     = l0;
        *(__nv_bfloat162*)(sBlo + k * LDB + n4 + 2) = l1;
    }
    __syncthreads();

    // warp grid: 4 (M) x 2 (N); warp tile 32x32 = 2x2 wmma 16x16x16 frags
    const int wm = wid & 3, wn = wid >> 2;
    wmma::fragment<wmma::accumulator, 16, 16, 16, float> c[2][2];
#pragma unroll
    for (int i = 0; i < 2; ++i)
#pragma unroll
        for (int j = 0; j < 2; ++j) wmma::fill_fragment(c[i][j], 0.f);

#pragma unroll
    for (int kk = 0; kk < 8; ++kk) {
        wmma::fragment<wmma::matrix_a, 16, 16, 16, __nv_bfloat16, wmma::row_major> ah[2], al[2];
        wmma::fragment<wmma::matrix_b, 16, 16, 16, __nv_bfloat16, wmma::row_major> bh[2], bl[2];
#pragma unroll
        for (int i = 0; i < 2; ++i) {
            const int r = (wm * 32 + i * 16) * LDA + kk * 16;
            wmma::load_matrix_sync(ah[i], sAhi + r, LDA);
            wmma::load_matrix_sync(al[i], sAlo + r, LDA);
        }
#pragma unroll
        for (int j = 0; j < 2; ++j) {
            const int r = (kk * 16) * LDB + wn * 32 + j * 16;
            wmma::load_matrix_sync(bh[j], sBhi + r, LDB);
            wmma::load_matrix_sync(bl[j], sBlo + r, LDB);
        }
#pragma unroll
        for (int i = 0; i < 2; ++i)
#pragma unroll
            for (int j = 0; j < 2; ++j) {
                wmma::mma_sync(c[i][j], ah[i], bh[j], c[i][j]);
                wmma::mma_sync(c[i][j], ah[i], bl[j], c[i][j]);
                wmma::mma_sync(c[i][j], al[i], bh[j], c[i][j]);
            }
    }

    // epilogue: stage frags through (now-reusable) smem, add bias/relu, store
    __syncthreads();
    float* stg = (float*)(s_raw) + wid * 1280;   // per-warp [32][40]
#pragma unroll
    for (int i = 0; i < 2; ++i)
#pragma unroll
        for (int j = 0; j < 2; ++j)
            wmma::store_matrix_sync(stg + i * 16 * 40 + j * 16, c[i][j], 40,
                                    wmma::mem_row_major);
    __syncwarp();

    int gr = row0 + wm * 32 + lane;
    if (gr < N_NODES) {
        const int cbase = col0 + wn * 32;
#pragma unroll
        for (int c4 = 0; c4 < 8; ++c4) {
            float4 bv = *(const float4*)(bias + cbase + c4 * 4);
            float4 v  = *(const float4*)(stg + lane * 40 + c4 * 4);
            float4 o;
            o.x = v.x + bv.x; o.y = v.y + bv.y;
            o.z = v.z + bv.z; o.w = v.w + bv.w;
            if (RELU) {
                o.x = fmaxf(o.x, 0.f); o.y = fmaxf(o.y, 0.f);
                o.z = fmaxf(o.z, 0.f); o.w = fmaxf(o.w, 0.f);
            }
            *(float4*)(out + (size_t)gr * NC + cbase + c4 * 4) = o;
        }
    }
}

// ---------------- edge_index tail (tuple second output) ---------------------
__global__ void edge_cast_kernel(float* __restrict__ out, int E) {
    int i = blockIdx.x * blockDim.x + threadIdx.x;
    if (i >= 2 * E) return;
    int v = (i < E) ? g_src[i] : g_dst[i - E];
    out[i] = (float)v;
}
__global__ void edge_copy64_kernel(long long* __restrict__ out, int E) {
    int i = blockIdx.x * blockDim.x + threadIdx.x;
    if (i >= 2 * E) return;
    int v = (i < E) ? g_src[i] : g_dst[i - E];
    out[i] = (long long)v;
}

// ---------------- launch -----------------------------------------------------
extern "C" void kernel_launch(void* const* d_in, const int* in_sizes, int n_in,
                              void* d_out, int out_size) {
    const float* x  = (const float*)d_in[0];
    const void*  ei = d_in[1];
    const float* W1 = (const float*)d_in[2];
    const float* b1 = (const float*)d_in[3];
    const float* W2 = (const float*)d_in[4];
    const float* b2 = (const float*)d_in[5];
    const float* W3 = (const float*)d_in[6];
    const float* b3 = (const float*)d_in[7];
    float* out = (float*)d_out;

    const int E = in_sizes[1] / 2;

    const int NTHR = 256;
    const int nodeBlocks  = (N_NODES + NTHR - 1) / NTHR;
    const int edgeBlocks  = (E + NTHR - 1) / NTHR;
    const int edge2Blocks = (2 * E + NTHR - 1) / NTHR;
    const int gatherBlocks = (N_NODES + 7) / 8;
    const dim3 g128(128 / 64, (N_NODES + 127) / 128);
    const dim3 g256(256 / 64, (N_NODES + 127) / 128);

    // edge dtype detection + normalization
    detect_init_kernel<<<1, 32>>>();
    detect_scan_kernel<<<edgeBlocks, NTHR>>>((const unsigned*)ei, 2 * E);
    convert_edges_kernel<<<edge2Blocks, NTHR>>>(ei, E);

    // degrees -> norms, CSR build
    zero_counts_kernel<<<nodeBlocks, NTHR>>>();
    degree_kernel<<<edgeBlocks, NTHR>>>(E);
    norm_kernel<<<nodeBlocks, NTHR>>>();
    scan1_kernel<<<NB_SCAN, 1024>>>();
    scan2_kernel<<<1, 128>>>();
    scan3_kernel<<<nodeBlocks, NTHR>>>(E);
    fill_csr_kernel<<<edgeBlocks, NTHR>>>(E);

    // layer 1: x -> g_h1
    gather_kernel<0><<<gatherBlocks, NTHR>>>(x);
    wmma_gemm_kernel<128, true, 1><<<g128, NTHR>>>(W1, b1, nullptr);

    // layer 2: g_h1 -> g_h2
    gather_kernel<1><<<gatherBlocks, NTHR>>>(nullptr);
    wmma_gemm_kernel<128, true, 2><<<g128, NTHR>>>(W2, b2, nullptr);

    // layer 3: g_h2 -> out, 256 cols, no relu
    gather_kernel<2><<<gatherBlocks, NTHR>>>(nullptr);
    wmma_gemm_kernel<256, false, 0><<<g256, NTHR>>>(W3, b3, out);

    // tuple tail: edge_index passthrough, if the harness compares it
    const long long HOUT = (long long)N_NODES * 256;
    const long long extra = (long long)out_size - HOUT;
    if (extra == 2LL * E) {
        edge_cast_kernel<<<edge2Blocks, NTHR>>>(out + HOUT, E);
    } else if (extra == 4LL * E) {
        edge_copy64_kernel<<<edge2Blocks, NTHR>>>((long long*)(out + HOUT), E);
    }
}